// round 17
// baseline (speedup 1.0000x reference)
#include <cuda_runtime.h>

// LovaszSoftmaxV1 — histogram/Abel-summation (no sort). R17 (base = R16):
// prep: 2-pixel software pipeline per thread (38 front-batched loads; B's
// loads hide A's compute/store tail), same 1-px-coalesced layout per step.
// minpos: 8 px/thread for deeper MLP. Layouts otherwise untouched.

#define LSV_CLS  19
#define LSV_HW   (384 * 384)           // 147456
#define LSV_MPIX (8 * LSV_HW)          // 1179648
#define LSV_BINS 2048
#define LSV_KPB  2                     // bins per thread in scan

#define LSV_MPB  2048                  // minpos: pixels per block (256 x 8)
#define LSV_MNB  (LSV_MPIX / LSV_MPB)  // 576
#define LSV_PPB  512                   // prep: pixels per block (256 x 2)
#define LSV_PNB  (LSV_MPIX / LSV_PPB)  // 2304

__device__ unsigned int lsvH_hneg[LSV_CLS * LSV_BINS];
__device__ unsigned int lsvH_hpos[LSV_CLS * LSV_BINS];
__device__ int          lsvH_minbin[LSV_CLS];
__device__ double       lsvH_cls_loss[LSV_CLS];
__device__ int          lsvH_lbl_is32;

__device__ __forceinline__ int lsvH_bin(float e) {
    int b = (int)(e * (float)LSV_BINS);
    return min(max(b, 0), LSV_BINS - 1);
}

// ---------------------------------------------------------------------------
__global__ void lsvH_zero() {
    int i = blockIdx.x * blockDim.x + threadIdx.x;
    if (i < LSV_CLS * LSV_BINS) { lsvH_hneg[i] = 0u; lsvH_hpos[i] = 0u; }
    if (i < LSV_CLS) lsvH_minbin[i] = 0x7fffffff;
    if (i == 0) lsvH_lbl_is32 = 0;
}

// ---------------------------------------------------------------------------
// Label dtype detector (int32 vs int64): odd int32-words of an int64(<19)
// little-endian buffer are all zero.
// ---------------------------------------------------------------------------
__global__ void __launch_bounds__(256) lsvH_detect(const int* __restrict__ w) {
    int i = blockIdx.x * blockDim.x + threadIdx.x;
    int idx = 2 * i + 1;
    int v = (idx < LSV_MPIX) ? w[idx] : 0;
    for (int off = 16; off > 0; off >>= 1)
        v |= __shfl_down_sync(0xffffffffu, v, off);
    if ((threadIdx.x & 31) == 0 && v != 0) atomicOr(&lsvH_lbl_is32, 1);
}

// ---------------------------------------------------------------------------
// Kernel 1: min positive bin per class — online softmax, 8 px/thread strided
// by 256 (every access = 1 line/warp; 8 independent LDGs per class-iter).
// ---------------------------------------------------------------------------
__global__ void __launch_bounds__(256) lsvH_minpos(
    const float* __restrict__ logits,
    const int* __restrict__ lblw)
{
    __shared__ int smin[LSV_CLS];
    int tid = threadIdx.x;
    if (tid < LSV_CLS) smin[tid] = 0x7fffffff;
    __syncthreads();

    int base_m = blockIdx.x * LSV_MPB + tid;
    int n  = base_m / LSV_HW;          // whole block shares one image
    int hw0 = base_m - n * LSV_HW;
    const float* lg = logits + (size_t)n * (LSV_CLS * LSV_HW) + hw0;
    int is32 = lsvH_lbl_is32;

    int lb[8];
    float s[8], evlb[8];
#pragma unroll
    for (int i = 0; i < 8; i++) {
        int m = base_m + i * 256;
        lb[i] = is32 ? lblw[m] : lblw[2 * m];
        s[i] = 0.f; evlb[i] = 0.f;
    }
#pragma unroll
    for (int c = 0; c < LSV_CLS; c++) {
        const float* row = lg + (size_t)c * LSV_HW;
#pragma unroll
        for (int i = 0; i < 8; i++) {
            float ev = __expf(__ldcs(row + i * 256));
            s[i] += ev;
            if (c == lb[i]) evlb[i] = ev;
        }
    }
#pragma unroll
    for (int i = 0; i < 8; i++) {
        if ((unsigned)lb[i] < LSV_CLS) {
            float e = 1.0f - evlb[i] / s[i];
            atomicMin(&smin[lb[i]], lsvH_bin(e));
        }
    }
    __syncthreads();
    if (tid < LSV_CLS && smin[tid] != 0x7fffffff)
        atomicMin(&lsvH_minbin[tid], smin[tid]);
}

// ---------------------------------------------------------------------------
// Kernel 2: prep, 2-pixel software pipeline. All 38 loads issued up front;
// pixel B's loads are in flight while pixel A's exp/store/atomic tail runs.
// 64-reg budget (4 blocks/SM) keeps both arrays register-resident.
// ---------------------------------------------------------------------------
__global__ void __launch_bounds__(256, 4) lsvH_prep(
    const float* __restrict__ logits,
    const int* __restrict__ lblw,
    float* __restrict__ errs)
{
    __shared__ int smb[LSV_CLS];
    int tid = threadIdx.x;
    if (tid < LSV_CLS) {
        int mb = lsvH_minbin[tid];
        smb[tid] = (mb == 0x7fffffff) ? 0 : mb;
    }
    __syncthreads();

    int mA = blockIdx.x * LSV_PPB + tid;       // chunk A pixel
    int mB = mA + 256;                          // chunk B pixel
    int n  = mA / LSV_HW;                       // 512-px block within one image
    const float* lgA = logits + (size_t)n * (LSV_CLS * LSV_HW) + (mA - n * LSV_HW);
    const float* lgB = lgA + 256;
    int is32 = lsvH_lbl_is32;

    int lbA = is32 ? lblw[mA] : lblw[2 * mA];
    int lbB = is32 ? lblw[mB] : lblw[2 * mB];

    float vA[LSV_CLS], vB[LSV_CLS];
#pragma unroll
    for (int c = 0; c < LSV_CLS; c++)
        vA[c] = __ldcs(lgA + (size_t)c * LSV_HW);
#pragma unroll
    for (int c = 0; c < LSV_CLS; c++)
        vB[c] = __ldcs(lgB + (size_t)c * LSV_HW);

    // --- process A (B loads still landing) ---
    float sA = 0.f;
#pragma unroll
    for (int c = 0; c < LSV_CLS; c++) {
        vA[c] = __expf(vA[c]);
        sA += vA[c];
    }
    float invA = 1.0f / sA;
#pragma unroll
    for (int c = 0; c < LSV_CLS; c++) {
        float p = vA[c] * invA;
        bool g = (c == lbA);
        float e = g ? (1.0f - p) : p;
        __stcs(errs + (size_t)c * LSV_MPIX + mA, e);
        int bin = lsvH_bin(e);
        if (bin >= smb[c])
            atomicAdd((g ? lsvH_hpos : lsvH_hneg) + c * LSV_BINS + bin, 1u);
    }

    // --- process B ---
    float sB = 0.f;
#pragma unroll
    for (int c = 0; c < LSV_CLS; c++) {
        vB[c] = __expf(vB[c]);
        sB += vB[c];
    }
    float invB = 1.0f / sB;
#pragma unroll
    for (int c = 0; c < LSV_CLS; c++) {
        float p = vB[c] * invB;
        bool g = (c == lbB);
        float e = g ? (1.0f - p) : p;
        __stcs(errs + (size_t)c * LSV_MPIX + mB, e);
        int bin = lsvH_bin(e);
        if (bin >= smb[c])
            atomicAdd((g ? lsvH_hpos : lsvH_hneg) + c * LSV_BINS + bin, 1u);
    }
}

// ---------------------------------------------------------------------------
// Scan: per-class Lovasz loss from split histograms (single pass, one fp64
// div per nonempty bin). j(cnt,cp) = 1 - (P-cp)/(P+cnt-cp), j(0,0) := 0.
// ---------------------------------------------------------------------------
__global__ void __launch_bounds__(1024) lsvH_scan() {
    const int c = blockIdx.x;
    const unsigned int* hn = lsvH_hneg + (size_t)c * LSV_BINS;
    const unsigned int* hp = lsvH_hpos + (size_t)c * LSV_BINS;
    int t = threadIdx.x, lane = t & 31, wid = t >> 5;

    unsigned int xn[LSV_KPB], xp[LSV_KPB];
    unsigned long long tot = 0ull;   // count | positives<<32
#pragma unroll
    for (int k = 0; k < LSV_KPB; k++) {
        int b = LSV_BINS - 1 - (t * LSV_KPB + k);
        xn[k] = hn[b]; xp[k] = hp[b];
        tot += (unsigned long long)(xn[k] + xp[k])
             + ((unsigned long long)xp[k] << 32);
    }

    __shared__ unsigned long long wsum[32];
    unsigned long long v = tot;
#pragma unroll
    for (int off = 1; off < 32; off <<= 1) {
        unsigned long long u = __shfl_up_sync(0xffffffffu, v, off);
        if (lane >= off) v += u;
    }
    if (lane == 31) wsum[wid] = v;
    __syncthreads();
    if (wid == 0) {
        unsigned long long w = wsum[lane];
#pragma unroll
        for (int off = 1; off < 32; off <<= 1) {
            unsigned long long u = __shfl_up_sync(0xffffffffu, w, off);
            if (lane >= off) w += u;
        }
        wsum[lane] = w;
    }
    __syncthreads();
    unsigned long long excl = v - tot;
    if (wid > 0) excl += wsum[wid - 1];
    long long P = (long long)(wsum[31] >> 32);

    long long cnt = (long long)(excl & 0xffffffffull);
    long long cp  = (long long)(excl >> 32);
    double jprev = (cnt == 0) ? 0.0
                 : 1.0 - (double)(P - cp) / (double)(P + cnt - cp);
    double loss = 0.0;
#pragma unroll
    for (int k = 0; k < LSV_KPB; k++) {
        int b = LSV_BINS - 1 - (t * LSV_KPB + k);
        long long nb = (long long)xn[k] + xp[k];
        if (nb > 0) {
            cnt += nb; cp += xp[k];
            double j1 = 1.0 - (double)(P - cp) / (double)(P + cnt - cp);
            loss += (((double)b + 0.5) / (double)LSV_BINS) * (j1 - jprev);
            jprev = j1;
        }
    }

    __shared__ double sl[32];
#pragma unroll
    for (int off = 16; off > 0; off >>= 1)
        loss += __shfl_down_sync(0xffffffffu, loss, off);
    if (lane == 0) sl[wid] = loss;
    __syncthreads();
    if (wid == 0) {
        double l = sl[lane];
#pragma unroll
        for (int off = 16; off > 0; off >>= 1)
            l += __shfl_down_sync(0xffffffffu, l, off);
        if (lane == 0) lsvH_cls_loss[c] = l;
    }
}

// ---------------------------------------------------------------------------
__global__ void lsvH_finalize(float* __restrict__ out) {
    double s = 0.0;
#pragma unroll
    for (int c = 0; c < LSV_CLS; c++) s += lsvH_cls_loss[c];
    out[0] = (float)(s / (double)LSV_CLS);
}

// ---------------------------------------------------------------------------
extern "C" void kernel_launch(void* const* d_in, const int* in_sizes, int n_in,
                              void* d_out, int out_size) {
    const float* logits = (const float*)d_in[0];
    const int*   lblw   = (const int*)d_in[1];
    float* out = (float*)d_out;

    const long long full = (long long)LSV_CLS * LSV_MPIX;
    long long off = (long long)out_size - full;
    if (off < 0) off = 0;
    float* errs_ptr = out + off;

    lsvH_zero<<<(LSV_CLS * LSV_BINS + 255) / 256, 256>>>();
    lsvH_detect<<<(LSV_MPIX / 2 + 255) / 256, 256>>>(lblw);
    lsvH_minpos<<<LSV_MNB, 256>>>(logits, lblw);
    lsvH_prep<<<LSV_PNB, 256>>>(logits, lblw, errs_ptr);
    lsvH_scan<<<LSV_CLS, 1024>>>();
    if (off > 0) lsvH_finalize<<<1, 1>>>(out);
}